// round 1
// baseline (speedup 1.0000x reference)
#include <cuda_runtime.h>

// Problem constants (fixed by setup_inputs)
#define B 8
#define N 2048
#define BN (B * N)
#define DELTA 1e-7f

// Persistent state (scratch) — __device__ globals per allocation rules
__device__ float g_pop[BN];          // populations
__device__ float g_sir[BN * 12];     // SIR features, grows 3 -> 6 -> 12
__device__ float g_odout[BN];        // per-row OD_out of current iteration
__device__ float g_colsum[BN * 7];   // column accumulators: k=0 -> OD_in, k=1..F -> SIR_in

// ---------------------------------------------------------------------------
// init: unpack input_feature (B,N,4) -> pop + SIR[0..2]; zero column sums
// ---------------------------------------------------------------------------
__global__ void init_kernel(const float* __restrict__ inp) {
    int t = blockIdx.x * blockDim.x + threadIdx.x;
    if (t >= BN) return;
    float4 v = reinterpret_cast<const float4*>(inp)[t];
    g_pop[t] = v.x;
    g_sir[t * 12 + 0] = v.y;
    g_sir[t * 12 + 1] = v.z;
    g_sir[t * 12 + 2] = v.w;
#pragma unroll
    for (int k = 0; k < 7; k++) g_colsum[t * 7 + k] = 0.0f;
}

// ---------------------------------------------------------------------------
// pass: single-DRAM-pass per iteration.
//   grid = B * (N/64) CTAs, 512 threads.
//   Phase 1: row sums + scale + weights (16 warps x 4 rows)
//   Phase 2: weighted column reduction over the 64-row tile (L1/L2 re-read)
// ---------------------------------------------------------------------------
template <int F>
__global__ void __launch_bounds__(512) pass_kernel(const float* __restrict__ od_all, int idx) {
    constexpr int K = F + 1;          // weight count: OD_in + F SIR features
    constexpr int ROWS = 64;

    __shared__ float s_w[ROWS][8];    // padded to 8 for clean addressing

    const int b    = blockIdx.x >> 5;         // 32 tiles per batch
    const int tile = blockIdx.x & 31;
    const int i0   = tile * ROWS;
    const int tid  = threadIdx.x;
    const int warp = tid >> 5;
    const int lane = tid & 31;

    const float* OD = od_all + ((size_t)(b * 2 + idx)) * N * N;

    // -------- Phase 1: row sums and weights --------
#pragma unroll
    for (int q = 0; q < 4; q++) {
        const int rl = warp * 4 + q;          // local row 0..63
        const int i  = i0 + rl;
        const float4* row4 = reinterpret_cast<const float4*>(OD + (size_t)i * N);
        float sum = 0.0f;
#pragma unroll 4
        for (int t = lane; t < N / 4; t += 32) {
            float4 v = row4[t];
            sum += (v.x + v.y) + (v.z + v.w);
        }
#pragma unroll
        for (int o = 16; o > 0; o >>= 1) sum += __shfl_xor_sync(0xffffffffu, sum, o);

        if (lane == 0) {
            const int gi = b * N + i;
            float pop = g_pop[gi];
            float den = DELTA + sum;
            float ratio = (den == 0.0f) ? 0.0f : pop / den;
            float s = (ratio < 1.0f) ? ratio : 1.0f;
            g_odout[gi] = s * sum;                       // OD_out for this row
            float dp = DELTA + pop;
            s_w[rl][0] = s;
#pragma unroll
            for (int f = 0; f < F; f++) {
                float sv = g_sir[gi * 12 + f];
                float sn = (dp == 0.0f) ? 0.0f : sv / dp; // SIR_n
                s_w[rl][1 + f] = s * sn;
            }
        }
    }
    __syncthreads();

    // -------- Phase 2: weighted column reduction --------
    // Each thread owns 4 consecutive columns (one float4 per row load).
    const int j4 = tid * 4;
    float acc[4][K];
#pragma unroll
    for (int c = 0; c < 4; c++)
#pragma unroll
        for (int k = 0; k < K; k++) acc[c][k] = 0.0f;

    const float4* odb = reinterpret_cast<const float4*>(OD);
#pragma unroll 4
    for (int r = 0; r < ROWS; r++) {
        float4 v = __ldg(&odb[((size_t)(i0 + r) * N + j4) >> 2]);
#pragma unroll
        for (int k = 0; k < K; k++) {
            float w = s_w[r][k];
            acc[0][k] = fmaf(v.x, w, acc[0][k]);
            acc[1][k] = fmaf(v.y, w, acc[1][k]);
            acc[2][k] = fmaf(v.z, w, acc[2][k]);
            acc[3][k] = fmaf(v.w, w, acc[3][k]);
        }
    }

    // flush partials (spread addresses -> cheap REDG)
#pragma unroll
    for (int c = 0; c < 4; c++) {
        float* dst = &g_colsum[((size_t)b * N + j4 + c) * 7];
#pragma unroll
        for (int k = 0; k < K; k++) atomicAdd(&dst[k], acc[c][k]);
    }
}

// ---------------------------------------------------------------------------
// update: pop/SIR state transition; re-zero colsum for the next iteration
// ---------------------------------------------------------------------------
template <int F>
__global__ void update_kernel() {
    int t = blockIdx.x * blockDim.x + threadIdx.x;
    if (t >= BN) return;
    float pop    = g_pop[t];
    float od_out = g_odout[t];
    float od_in  = g_colsum[t * 7 + 0];
    float dp     = DELTA + pop;

    float stay[F], sin_[F];
#pragma unroll
    for (int f = 0; f < F; f++) {
        float sv = g_sir[t * 12 + f];
        float sn = (dp == 0.0f) ? 0.0f : sv / dp;
        stay[f] = sv - od_out * sn;
        sin_[f] = g_colsum[t * 7 + 1 + f];
    }
    g_pop[t] = pop - od_out + od_in;
#pragma unroll
    for (int f = 0; f < F; f++) {
        g_sir[t * 12 + f]     = stay[f];
        g_sir[t * 12 + F + f] = sin_[f];
    }
#pragma unroll
    for (int k = 0; k < 7; k++) g_colsum[t * 7 + k] = 0.0f;
}

// ---------------------------------------------------------------------------
// final: out[:, :, 0] = pop; out[:, :, 1:65] = relu(SIR12 @ kernel + bias)
// ---------------------------------------------------------------------------
__global__ void final_kernel(const float* __restrict__ kern,
                             const float* __restrict__ bias,
                             float* __restrict__ out) {
    int g = blockIdx.x * blockDim.x + threadIdx.x;
    if (g >= BN * 64) return;
    int row = g >> 6;
    int c   = g & 63;
    float acc = __ldg(&bias[c]);
#pragma unroll
    for (int f = 0; f < 12; f++)
        acc = fmaf(g_sir[row * 12 + f], __ldg(&kern[f * 64 + c]), acc);
    acc = fmaxf(acc, 0.0f);
    float* orow = out + (size_t)row * 65;
    orow[1 + c] = acc;
    if (c == 0) orow[0] = g_pop[row];
}

// ---------------------------------------------------------------------------
extern "C" void kernel_launch(void* const* d_in, const int* in_sizes, int n_in,
                              void* d_out, int out_size) {
    const float* inp  = (const float*)d_in[0];  // input_feature (8,2048,4)
    const float* od   = (const float*)d_in[1];  // OD_all (8,2,2048,2048)
    const float* kern = (const float*)d_in[2];  // kernel (12,64)
    const float* bias = (const float*)d_in[3];  // bias (64)
    float* out = (float*)d_out;                 // (8,2048,65)

    init_kernel<<<BN / 256, 256>>>(inp);

    pass_kernel<3><<<B * (N / 64), 512>>>(od, 0);
    update_kernel<3><<<BN / 256, 256>>>();

    pass_kernel<6><<<B * (N / 64), 512>>>(od, 1);
    update_kernel<6><<<BN / 256, 256>>>();

    final_kernel<<<(BN * 64) / 256, 256>>>(kern, bias, out);
}